// round 3
// baseline (speedup 1.0000x reference)
#include <cuda_runtime.h>
#include <cuda_fp16.h>

#define NN 4096
#define DD 128
#define ITERS 100
#define GRID_SINK 128
#define EPSV 1e-8f
#define MUV (1.0f / 4096.0f)

// ---------------- static device scratch (allocation-free rule) ----------------
__device__ __align__(256) __half g_Kh[3ULL * NN * NN];   // 96 MB fp16
__device__ __align__(256) __half g_Ch[3ULL * NN * NN];   // 96 MB fp16
__device__ __align__(256) float g_u[3][NN];
__device__ __align__(256) float g_v[3][NN];
__device__ __align__(256) float g_sq[3][NN];
__device__ double g_part[3 * GRID_SINK];
__device__ unsigned g_cnt = 0;
__device__ volatile unsigned g_gen = 0;

__device__ __forceinline__ float2 pack4h(float a, float b, float c, float d) {
    __half2 h0 = __floats2half2_rn(a, b);
    __half2 h1 = __floats2half2_rn(c, d);
    float2 r;
    r.x = __uint_as_float(*reinterpret_cast<unsigned*>(&h0));
    r.y = __uint_as_float(*reinterpret_cast<unsigned*>(&h1));
    return r;
}

// ---------------- grid-wide barrier (single-wave persistent kernel) -----------
__device__ __forceinline__ void grid_barrier() {
    __syncthreads();
    if (threadIdx.x == 0) {
        __threadfence();
        unsigned gen = g_gen;
        if (atomicAdd(&g_cnt, 1u) == GRID_SINK - 1) {
            atomicExch(&g_cnt, 0u);
            __threadfence();
            g_gen = gen + 1;
        } else {
            while (g_gen == gen) { }
        }
        __threadfence();
    }
    __syncthreads();
}

// ---------------- row squared norms for all 3 inputs ---------------------------
__global__ void rowsq_kernel(const float* __restrict__ z0, const float* __restrict__ z1,
                             const float* __restrict__ z2) {
    int gw = (blockIdx.x * blockDim.x + threadIdx.x) >> 5;
    int lane = threadIdx.x & 31;
    int which = gw >> 12, row = gw & 4095;
    const float* src = which == 0 ? z0 : (which == 1 ? z1 : z2);
    float4 v = *(const float4*)(src + (size_t)row * DD + lane * 4);
    float s = v.x * v.x + v.y * v.y + v.z * v.z + v.w * v.w;
#pragma unroll
    for (int o = 16; o; o >>= 1) s += __shfl_xor_sync(0xffffffffu, s, o);
    if (lane == 0) g_sq[which][row] = s;
}

// ---------------- build C and K for all 3 pairs (tiled fp32 GEMM + exp) -------
__global__ void __launch_bounds__(256) build_kernel(const float* __restrict__ z0,
                                                    const float* __restrict__ z1,
                                                    const float* __restrict__ z2) {
    __shared__ float sx[64][33];
    __shared__ float sy[64][33];
    const int pa[3] = {0, 0, 1};
    const int pb[3] = {1, 2, 2};
    const float* zz[3] = {z0, z1, z2};
    const int p = blockIdx.z;
    const float* x = zz[pa[p]];
    const float* y = zz[pb[p]];

    const int tid = threadIdx.x;
    const int tx = tid & 15, ty = tid >> 4;
    const int row0 = blockIdx.y << 6, col0 = blockIdx.x << 6;

    float acc[4][4] = {};

    for (int kc = 0; kc < DD; kc += 32) {
        __syncthreads();
#pragma unroll
        for (int q = 0; q < 2; q++) {
            int idx = tid + (q << 8);
            int r = idx >> 3, kk = (idx & 7) << 2;
            float4 a = *(const float4*)(x + (size_t)(row0 + r) * DD + kc + kk);
            sx[r][kk] = a.x; sx[r][kk + 1] = a.y; sx[r][kk + 2] = a.z; sx[r][kk + 3] = a.w;
            float4 b = *(const float4*)(y + (size_t)(col0 + r) * DD + kc + kk);
            sy[r][kk] = b.x; sy[r][kk + 1] = b.y; sy[r][kk + 2] = b.z; sy[r][kk + 3] = b.w;
        }
        __syncthreads();
#pragma unroll
        for (int k = 0; k < 32; k++) {
            float xa[4], yb[4];
#pragma unroll
            for (int a = 0; a < 4; a++) xa[a] = sx[ty * 4 + a][k];
#pragma unroll
            for (int b = 0; b < 4; b++) yb[b] = sy[tx * 4 + b][k];
#pragma unroll
            for (int a = 0; a < 4; a++)
#pragma unroll
                for (int b = 0; b < 4; b++)
                    acc[a][b] = fmaf(xa[a], yb[b], acc[a][b]);
        }
    }

    float xs[4], ys[4];
#pragma unroll
    for (int a = 0; a < 4; a++) xs[a] = g_sq[pa[p]][row0 + ty * 4 + a];
#pragma unroll
    for (int b = 0; b < 4; b++) ys[b] = g_sq[pb[p]][col0 + tx * 4 + b];

    const size_t base = (size_t)p * NN * NN;
#pragma unroll
    for (int a = 0; a < 4; a++) {
        size_t off = base + (size_t)(row0 + ty * 4 + a) * NN + col0 + tx * 4;
        float c[4], kk[4];
#pragma unroll
        for (int b = 0; b < 4; b++) {
            c[b] = fmaxf(xs[a] + ys[b] - 2.0f * acc[a][b], 0.0f);
            kk[b] = __expf(-20.0f * c[b]);   // 1/REG = 20
        }
        *(float2*)(g_Kh + off) = pack4h(kk[0], kk[1], kk[2], kk[3]);
        __stcs((float2*)(g_Ch + off), pack4h(c[0], c[1], c[2], c[3]));
    }
}

// ---------------- persistent fused 3-pair Sinkhorn -----------------------------
__global__ void __launch_bounds__(256, 1) sinkhorn_kernel() {
    __shared__ float svec[NN];        // staged u or v of current pair (16 KB)
    __shared__ float4 red[8][8];
    const int c = blockIdx.x;
    const int tid = threadIdx.x;
    const int lane = tid & 31, w = tid >> 5;

    if (tid < 32) {
#pragma unroll
        for (int p = 0; p < 3; p++) g_u[p][c * 32 + tid] = 1.0f;
    }
    grid_barrier();

    for (int it = 0; it < ITERS; it++) {
        // ---- Phase A: t = K^T u ; v = nu/(t+eps). CTA owns 32 columns/pair. ---
#pragma unroll 1
        for (int p = 0; p < 3; p++) {
            __syncthreads();
            {
                float4* s4 = (float4*)svec;
                const float4* gu4 = (const float4*)g_u[p];
#pragma unroll
                for (int q = 0; q < 4; q++) s4[tid + q * 256] = gu4[tid + q * 256];
            }
            __syncthreads();

            // lane tile: 4 columns (lane&7)*4, row offset lane>>3 (stride 4)
            const int colq = (lane & 7) << 2;
            const int ro = lane >> 3;
            const __half* Kbase = g_Kh + (size_t)p * NN * NN +
                                  (size_t)(w * 512 + ro) * NN + c * 32 + colq;
            const float* up = svec + w * 512 + ro;
            float4 acc = make_float4(0.f, 0.f, 0.f, 0.f);
#pragma unroll 8
            for (int i = 0; i < 128; i++) {
                float2 kraw = __ldcg((const float2*)(Kbase + (size_t)4 * i * NN));
                float uu = up[4 * i];
                __half2 h0 = *reinterpret_cast<__half2*>(&kraw.x);
                __half2 h1 = *reinterpret_cast<__half2*>(&kraw.y);
                float2 f0 = __half22float2(h0);
                float2 f1 = __half22float2(h1);
                acc.x = fmaf(f0.x, uu, acc.x);
                acc.y = fmaf(f0.y, uu, acc.y);
                acc.z = fmaf(f1.x, uu, acc.z);
                acc.w = fmaf(f1.y, uu, acc.w);
            }
            // combine the 4 row-offset groups (lane bits 3,4)
#pragma unroll
            for (int o = 8; o <= 16; o <<= 1) {
                acc.x += __shfl_xor_sync(0xffffffffu, acc.x, o);
                acc.y += __shfl_xor_sync(0xffffffffu, acc.y, o);
                acc.z += __shfl_xor_sync(0xffffffffu, acc.z, o);
                acc.w += __shfl_xor_sync(0xffffffffu, acc.w, o);
            }
            if (lane < 8) red[w][lane] = acc;
            __syncthreads();
            if (tid < 32) {
                int j = tid >> 2, comp = tid & 3;
                float t = 0.0f;
#pragma unroll
                for (int w2 = 0; w2 < 8; w2++) t += ((const float*)&red[w2][j])[comp];
                g_v[p][c * 32 + tid] = MUV / (t + EPSV);
            }
        }
        grid_barrier();

        // ---- Phase B: s = K v ; u = mu/(s+eps). CTA owns 32 rows/pair. --------
#pragma unroll 1
        for (int p = 0; p < 3; p++) {
            __syncthreads();
            {
                float4* s4 = (float4*)svec;
                const float4* gv4 = (const float4*)g_v[p];
#pragma unroll
                for (int q = 0; q < 4; q++) s4[tid + q * 256] = gv4[tid + q * 256];
            }
            __syncthreads();

            const float4* sv4 = (const float4*)svec;
#pragma unroll
            for (int rr = 0; rr < 4; rr++) {
                int row = c * 32 + w * 4 + rr;
                const float2* Kr = (const float2*)(g_Kh + (size_t)p * NN * NN +
                                                   (size_t)row * NN);
                float acc = 0.0f;
#pragma unroll 8
                for (int i = 0; i < 32; i++) {
                    float2 kraw = __ldcg(Kr + lane + i * 32);
                    float4 vv = sv4[lane + i * 32];
                    __half2 h0 = *reinterpret_cast<__half2*>(&kraw.x);
                    __half2 h1 = *reinterpret_cast<__half2*>(&kraw.y);
                    float2 f0 = __half22float2(h0);
                    float2 f1 = __half22float2(h1);
                    acc = fmaf(f0.x, vv.x, acc);
                    acc = fmaf(f0.y, vv.y, acc);
                    acc = fmaf(f1.x, vv.z, acc);
                    acc = fmaf(f1.y, vv.w, acc);
                }
#pragma unroll
                for (int o = 16; o; o >>= 1) acc += __shfl_xor_sync(0xffffffffu, acc, o);
                if (lane == 0) g_u[p][row] = MUV / (acc + EPSV);
            }
        }
        grid_barrier();
    }
}

// ---------------- loss = sum_ij u_i K_ij C_ij v_j (per pair) -------------------
__global__ void __launch_bounds__(256) loss_kernel() {
    __shared__ float svec[NN];
    __shared__ double sred[8];
    const int c = blockIdx.x;
    const int p = blockIdx.y;
    const int tid = threadIdx.x;
    const int lane = tid & 31, w = tid >> 5;

    {
        float4* s4 = (float4*)svec;
        const float4* gv4 = (const float4*)g_v[p];
#pragma unroll
        for (int q = 0; q < 4; q++) s4[tid + q * 256] = gv4[tid + q * 256];
    }
    __syncthreads();

    const float4* sv4 = (const float4*)svec;
    double dacc = 0.0;
#pragma unroll
    for (int rr = 0; rr < 4; rr++) {
        int row = c * 32 + w * 4 + rr;
        const float2* Kr = (const float2*)(g_Kh + (size_t)p * NN * NN + (size_t)row * NN);
        const float2* Cr = (const float2*)(g_Ch + (size_t)p * NN * NN + (size_t)row * NN);
        float acc = 0.0f;
#pragma unroll 4
        for (int i = 0; i < 32; i++) {
            float2 kraw = __ldcs(Kr + lane + i * 32);
            float2 craw = __ldcs(Cr + lane + i * 32);
            float4 vv = sv4[lane + i * 32];
            __half2 kh0 = *reinterpret_cast<__half2*>(&kraw.x);
            __half2 kh1 = *reinterpret_cast<__half2*>(&kraw.y);
            __half2 ch0 = *reinterpret_cast<__half2*>(&craw.x);
            __half2 ch1 = *reinterpret_cast<__half2*>(&craw.y);
            float2 k0 = __half22float2(kh0), k1 = __half22float2(kh1);
            float2 c0 = __half22float2(ch0), c1 = __half22float2(ch1);
            acc = fmaf(k0.x * c0.x, vv.x, acc);
            acc = fmaf(k0.y * c0.y, vv.y, acc);
            acc = fmaf(k1.x * c1.x, vv.z, acc);
            acc = fmaf(k1.y * c1.y, vv.w, acc);
        }
#pragma unroll
        for (int o = 16; o; o >>= 1) acc += __shfl_xor_sync(0xffffffffu, acc, o);
        if (lane == 0) dacc += (double)acc * (double)g_u[p][row];
    }
    if (lane == 0) sred[w] = dacc;
    __syncthreads();
    if (tid == 0) {
        double s = 0.0;
#pragma unroll
        for (int i = 0; i < 8; i++) s += sred[i];
        g_part[p * GRID_SINK + c] = s;
    }
}

// ---------------- final reduction ---------------------------------------------
__global__ void final_kernel(float* out) {
    __shared__ double sd[128];
    int t = threadIdx.x;
    double s = g_part[t] + g_part[t + 128] + g_part[t + 256];
    sd[t] = s;
    __syncthreads();
    for (int o = 64; o; o >>= 1) {
        if (t < o) sd[t] += sd[t + o];
        __syncthreads();
    }
    if (t == 0) out[0] = (float)(sd[0] / 3.0);
}

// ---------------- launch -------------------------------------------------------
extern "C" void kernel_launch(void* const* d_in, const int* in_sizes, int n_in,
                              void* d_out, int out_size) {
    const float* z0 = (const float*)d_in[0];
    const float* z1 = (const float*)d_in[1];
    const float* z2 = (const float*)d_in[2];

    rowsq_kernel<<<1536, 256>>>(z0, z1, z2);
    build_kernel<<<dim3(64, 64, 3), 256>>>(z0, z1, z2);
    sinkhorn_kernel<<<GRID_SINK, 256>>>();
    loss_kernel<<<dim3(GRID_SINK, 3), 256>>>();
    final_kernel<<<1, 128>>>((float*)d_out);
}

// round 4
// speedup vs baseline: 1.7680x; 1.7680x over previous
#include <cuda_runtime.h>
#include <cuda_fp16.h>
#include <cuda_fp8.h>

#define NN 4096
#define DD 128
#define ITERS 100
#define GRID_SINK 128
#define EPSV 1e-8f
#define MUV (1.0f / 4096.0f)
#define REGC 0.05f

// ---------------- static device scratch (allocation-free rule) ----------------
__device__ __align__(256) unsigned char g_K8[3ULL * NN * NN];  // 48 MB fp8 e4m3
__device__ __align__(256) float g_u[3][NN];
__device__ __align__(256) float g_tp[3][4][NN];                // phase-A partials
__device__ __align__(256) float g_sq[3][NN];
__device__ double g_part[3 * GRID_SINK];
__device__ unsigned g_cnt = 0;
__device__ volatile unsigned g_gen = 0;

// ---------------- fp8 helpers --------------------------------------------------
__device__ __forceinline__ unsigned enc4(float a, float b, float c, float d) {
    unsigned short lo = __nv_cvt_float2_to_fp8x2(make_float2(a, b), __NV_SATFINITE, __NV_E4M3);
    unsigned short hi = __nv_cvt_float2_to_fp8x2(make_float2(c, d), __NV_SATFINITE, __NV_E4M3);
    return (unsigned)lo | ((unsigned)hi << 16);
}

__device__ __forceinline__ void dec4(unsigned x, float* f) {
    __half2 h0, h1;
    *reinterpret_cast<__half2_raw*>(&h0) =
        __nv_cvt_fp8x2_to_halfraw2((__nv_fp8x2_storage_t)(x & 0xFFFFu), __NV_E4M3);
    *reinterpret_cast<__half2_raw*>(&h1) =
        __nv_cvt_fp8x2_to_halfraw2((__nv_fp8x2_storage_t)(x >> 16), __NV_E4M3);
    float2 a = __half22float2(h0), b = __half22float2(h1);
    f[0] = a.x; f[1] = a.y; f[2] = b.x; f[3] = b.y;
}

// ---------------- grid-wide barrier (single-wave persistent kernel) -----------
__device__ __forceinline__ void grid_barrier() {
    __syncthreads();
    if (threadIdx.x == 0) {
        __threadfence();
        unsigned gen = g_gen;
        if (atomicAdd(&g_cnt, 1u) == GRID_SINK - 1) {
            atomicExch(&g_cnt, 0u);
            __threadfence();
            g_gen = gen + 1;
        } else {
            while (g_gen == gen) { }
        }
        __threadfence();   // CCTL.IVALL: invalidates this SM's L1 for everyone
    }
    __syncthreads();
}

// ---------------- row squared norms for all 3 inputs ---------------------------
__global__ void rowsq_kernel(const float* __restrict__ z0, const float* __restrict__ z1,
                             const float* __restrict__ z2) {
    int gw = (blockIdx.x * blockDim.x + threadIdx.x) >> 5;
    int lane = threadIdx.x & 31;
    int which = gw >> 12, row = gw & 4095;
    const float* src = which == 0 ? z0 : (which == 1 ? z1 : z2);
    float4 v = *(const float4*)(src + (size_t)row * DD + lane * 4);
    float s = v.x * v.x + v.y * v.y + v.z * v.z + v.w * v.w;
#pragma unroll
    for (int o = 16; o; o >>= 1) s += __shfl_xor_sync(0xffffffffu, s, o);
    if (lane == 0) g_sq[which][row] = s;
}

// ---------------- build K (fp8) for all 3 pairs --------------------------------
__global__ void __launch_bounds__(256) build_kernel(const float* __restrict__ z0,
                                                    const float* __restrict__ z1,
                                                    const float* __restrict__ z2) {
    __shared__ float sx[64][33];
    __shared__ float sy[64][33];
    const int pa[3] = {0, 0, 1};
    const int pb[3] = {1, 2, 2};
    const float* zz[3] = {z0, z1, z2};
    const int p = blockIdx.z;
    const float* x = zz[pa[p]];
    const float* y = zz[pb[p]];

    const int tid = threadIdx.x;
    const int tx = tid & 15, ty = tid >> 4;
    const int row0 = blockIdx.y << 6, col0 = blockIdx.x << 6;

    float acc[4][4] = {};

    for (int kc = 0; kc < DD; kc += 32) {
        __syncthreads();
#pragma unroll
        for (int q = 0; q < 2; q++) {
            int idx = tid + (q << 8);
            int r = idx >> 3, kk = (idx & 7) << 2;
            float4 a = *(const float4*)(x + (size_t)(row0 + r) * DD + kc + kk);
            sx[r][kk] = a.x; sx[r][kk + 1] = a.y; sx[r][kk + 2] = a.z; sx[r][kk + 3] = a.w;
            float4 b = *(const float4*)(y + (size_t)(col0 + r) * DD + kc + kk);
            sy[r][kk] = b.x; sy[r][kk + 1] = b.y; sy[r][kk + 2] = b.z; sy[r][kk + 3] = b.w;
        }
        __syncthreads();
#pragma unroll
        for (int k = 0; k < 32; k++) {
            float xa[4], yb[4];
#pragma unroll
            for (int a = 0; a < 4; a++) xa[a] = sx[ty * 4 + a][k];
#pragma unroll
            for (int b = 0; b < 4; b++) yb[b] = sy[tx * 4 + b][k];
#pragma unroll
            for (int a = 0; a < 4; a++)
#pragma unroll
                for (int b = 0; b < 4; b++)
                    acc[a][b] = fmaf(xa[a], yb[b], acc[a][b]);
        }
    }

    float xs[4], ys[4];
#pragma unroll
    for (int a = 0; a < 4; a++) xs[a] = g_sq[pa[p]][row0 + ty * 4 + a];
#pragma unroll
    for (int b = 0; b < 4; b++) ys[b] = g_sq[pb[p]][col0 + tx * 4 + b];

    const size_t base = (size_t)p * NN * NN;
#pragma unroll
    for (int a = 0; a < 4; a++) {
        size_t off = base + (size_t)(row0 + ty * 4 + a) * NN + col0 + tx * 4;
        float kk[4];
#pragma unroll
        for (int b = 0; b < 4; b++) {
            float c = fmaxf(xs[a] + ys[b] - 2.0f * acc[a][b], 0.0f);
            kk[b] = fmaxf(__expf(-20.0f * c), 0.002f);   // clamp above fp8 flush-to-zero
        }
        *(unsigned*)(g_K8 + off) = enc4(kk[0], kk[1], kk[2], kk[3]);
    }
}

// ---------------- persistent fused 3-pair Sinkhorn (fp8 K) ---------------------
__global__ void __launch_bounds__(256, 1) sinkhorn_kernel() {
    __shared__ float svec[NN];          // phase B: v[4096]; phase A: u-slice[1024]
    __shared__ float red[8][128];
    const int c = blockIdx.x;
    const int tid = threadIdx.x;
    const int lane = tid & 31, w = tid >> 5;
    const int rb = c >> 5, cb = c & 31;   // phase-A tile: rows rb*1024.., cols cb*128..

    if (tid < 32) {
#pragma unroll
        for (int p = 0; p < 3; p++) g_u[p][c * 32 + tid] = 1.0f;
    }
    grid_barrier();

    for (int it = 0; it < ITERS; it++) {
        // ---- Phase A: partial t = K^T u over 1024-row x 128-col tile ----------
#pragma unroll 1
        for (int p = 0; p < 3; p++) {
            __syncthreads();
            ((float4*)svec)[tid] = ((const float4*)(g_u[p] + rb * 1024))[tid];  // u slice
            __syncthreads();

            const int colo = (lane & 15) << 3;   // 8 cols per lane
            const int ro = lane >> 4;            // row offset 0/1
            const uint2* Kp = (const uint2*)(g_K8 + (size_t)p * NN * NN +
                                             (size_t)(rb * 1024 + w * 128 + ro) * NN +
                                             cb * 128 + colo);
            const float* up = svec + w * 128 + ro;
            float acc[8] = {};
#pragma unroll 8
            for (int i = 0; i < 64; i++) {
                uint2 kr = __ldcg(Kp + (size_t)i * 1024);   // step 2 rows
                float uu = up[2 * i];
                float f[8];
                dec4(kr.x, f);
                dec4(kr.y, f + 4);
#pragma unroll
                for (int j = 0; j < 8; j++) acc[j] = fmaf(f[j], uu, acc[j]);
            }
#pragma unroll
            for (int j = 0; j < 8; j++)
                acc[j] += __shfl_xor_sync(0xffffffffu, acc[j], 16);
            if (lane < 16) {
#pragma unroll
                for (int j = 0; j < 8; j++) red[w][lane * 8 + j] = acc[j];
            }
            __syncthreads();
            if (tid < 128) {
                float t = red[0][tid];
#pragma unroll
                for (int w2 = 1; w2 < 8; w2++) t += red[w2][tid];
                g_tp[p][rb][cb * 128 + tid] = t;
            }
        }
        grid_barrier();

        // ---- Phase B: v = nu/(t+eps) (redundant), then u = mu/(K v + eps) -----
#pragma unroll 1
        for (int p = 0; p < 3; p++) {
            __syncthreads();
#pragma unroll
            for (int k2 = 0; k2 < 16; k2++) {
                int j = tid + k2 * 256;
                float t = g_tp[p][0][j] + g_tp[p][1][j] + g_tp[p][2][j] + g_tp[p][3][j];
                svec[j] = MUV / (t + EPSV);
            }
            __syncthreads();

            const float4* sv4 = (const float4*)svec;
#pragma unroll
            for (int rr = 0; rr < 4; rr++) {
                int row = c * 32 + w * 4 + rr;
                const uint2* Kr = (const uint2*)(g_K8 + (size_t)p * NN * NN +
                                                 (size_t)row * NN) + lane;
                float acc0 = 0.0f, acc1 = 0.0f;
#pragma unroll 4
                for (int i = 0; i < 16; i++) {
                    uint2 kr = __ldcg(Kr + i * 32);
                    float4 v0 = sv4[(lane + i * 32) * 2];
                    float4 v1 = sv4[(lane + i * 32) * 2 + 1];
                    float f[8];
                    dec4(kr.x, f);
                    dec4(kr.y, f + 4);
                    acc0 = fmaf(f[0], v0.x, acc0);
                    acc1 = fmaf(f[1], v0.y, acc1);
                    acc0 = fmaf(f[2], v0.z, acc0);
                    acc1 = fmaf(f[3], v0.w, acc1);
                    acc0 = fmaf(f[4], v1.x, acc0);
                    acc1 = fmaf(f[5], v1.y, acc1);
                    acc0 = fmaf(f[6], v1.z, acc0);
                    acc1 = fmaf(f[7], v1.w, acc1);
                }
                float acc = acc0 + acc1;
#pragma unroll
                for (int o = 16; o; o >>= 1) acc += __shfl_xor_sync(0xffffffffu, acc, o);
                if (lane == 0) g_u[p][row] = MUV / (acc + EPSV);
            }
        }
        grid_barrier();
    }
}

// ---------------- loss = sum_ij u_i K_ij C_ij v_j,  C = -reg*ln(K) -------------
__global__ void __launch_bounds__(256) loss_kernel() {
    __shared__ float svec[NN];
    __shared__ double sred[8];
    const int c = blockIdx.x;
    const int p = blockIdx.y;
    const int tid = threadIdx.x;
    const int lane = tid & 31, w = tid >> 5;

#pragma unroll
    for (int k2 = 0; k2 < 16; k2++) {
        int j = tid + k2 * 256;
        float t = g_tp[p][0][j] + g_tp[p][1][j] + g_tp[p][2][j] + g_tp[p][3][j];
        svec[j] = MUV / (t + EPSV);
    }
    __syncthreads();

    const float4* sv4 = (const float4*)svec;
    double dacc = 0.0;
#pragma unroll
    for (int rr = 0; rr < 4; rr++) {
        int row = c * 32 + w * 4 + rr;
        const uint2* Kr = (const uint2*)(g_K8 + (size_t)p * NN * NN + (size_t)row * NN) + lane;
        float acc = 0.0f;
#pragma unroll 2
        for (int i = 0; i < 16; i++) {
            uint2 kr = __ldcs(Kr + i * 32);
            float4 v0 = sv4[(lane + i * 32) * 2];
            float4 v1 = sv4[(lane + i * 32) * 2 + 1];
            float f[8];
            dec4(kr.x, f);
            dec4(kr.y, f + 4);
            float vv[8] = {v0.x, v0.y, v0.z, v0.w, v1.x, v1.y, v1.z, v1.w};
#pragma unroll
            for (int j = 0; j < 8; j++) {
                float cc = -REGC * __logf(fmaxf(f[j], 1e-30f));
                acc = fmaf(f[j] * cc, vv[j], acc);
            }
        }
#pragma unroll
        for (int o = 16; o; o >>= 1) acc += __shfl_xor_sync(0xffffffffu, acc, o);
        if (lane == 0) dacc += (double)acc * (double)g_u[p][row];
    }
    if (lane == 0) sred[w] = dacc;
    __syncthreads();
    if (tid == 0) {
        double s = 0.0;
#pragma unroll
        for (int i = 0; i < 8; i++) s += sred[i];
        g_part[p * GRID_SINK + c] = s;
    }
}

// ---------------- final reduction ---------------------------------------------
__global__ void final_kernel(float* out) {
    __shared__ double sd[128];
    int t = threadIdx.x;
    double s = g_part[t] + g_part[t + 128] + g_part[t + 256];
    sd[t] = s;
    __syncthreads();
    for (int o = 64; o; o >>= 1) {
        if (t < o) sd[t] += sd[t + o];
        __syncthreads();
    }
    if (t == 0) out[0] = (float)(sd[0] / 3.0);
}

// ---------------- launch -------------------------------------------------------
extern "C" void kernel_launch(void* const* d_in, const int* in_sizes, int n_in,
                              void* d_out, int out_size) {
    const float* z0 = (const float*)d_in[0];
    const float* z1 = (const float*)d_in[1];
    const float* z2 = (const float*)d_in[2];

    rowsq_kernel<<<1536, 256>>>(z0, z1, z2);
    build_kernel<<<dim3(64, 64, 3), 256>>>(z0, z1, z2);
    sinkhorn_kernel<<<GRID_SINK, 256>>>();
    loss_kernel<<<dim3(GRID_SINK, 3), 256>>>();
    final_kernel<<<1, 128>>>((float*)d_out);
}

// round 5
// speedup vs baseline: 3.5541x; 2.0102x over previous
#include <cuda_runtime.h>
#include <cuda_fp16.h>
#include <cuda_fp8.h>

#define NN 4096
#define DD 128
#define ITERS 100
#define GRID_SINK 128
#define EPSV 1e-8f
#define MUV (1.0f / 4096.0f)
#define REGC 0.05f
#define VSCALE 1024.0f

// ---------------- static device scratch (allocation-free rule) ----------------
__device__ __align__(256) unsigned char g_K8[3ULL * NN * NN];  // 48 MB fp8 e4m3
__device__ __align__(256) float g_u[3][NN];
__device__ __align__(256) float g_tp[3][4][NN];                // phase-A partials
__device__ __align__(256) float g_sq[3][NN];
__device__ double g_part[3 * GRID_SINK];
__device__ unsigned g_cnt = 0;
__device__ volatile unsigned g_gen = 0;

// ---------------- fp8 helpers --------------------------------------------------
__device__ __forceinline__ unsigned enc4(float a, float b, float c, float d) {
    unsigned short lo = __nv_cvt_float2_to_fp8x2(make_float2(a, b), __NV_SATFINITE, __NV_E4M3);
    unsigned short hi = __nv_cvt_float2_to_fp8x2(make_float2(c, d), __NV_SATFINITE, __NV_E4M3);
    return (unsigned)lo | ((unsigned)hi << 16);
}

__device__ __forceinline__ __half2 dec2h(unsigned short s) {
    __half2_raw r = __nv_cvt_fp8x2_to_halfraw2((__nv_fp8x2_storage_t)s, __NV_E4M3);
    return *reinterpret_cast<__half2*>(&r);
}

// decode 16 fp8 (uint4) -> 8 half2
__device__ __forceinline__ void dec16(uint4 k, __half2* h) {
    h[0] = dec2h((unsigned short)(k.x & 0xFFFFu));
    h[1] = dec2h((unsigned short)(k.x >> 16));
    h[2] = dec2h((unsigned short)(k.y & 0xFFFFu));
    h[3] = dec2h((unsigned short)(k.y >> 16));
    h[4] = dec2h((unsigned short)(k.z & 0xFFFFu));
    h[5] = dec2h((unsigned short)(k.z >> 16));
    h[6] = dec2h((unsigned short)(k.w & 0xFFFFu));
    h[7] = dec2h((unsigned short)(k.w >> 16));
}

__device__ __forceinline__ void dec4f(unsigned x, float* f) {
    float2 a = __half22float2(dec2h((unsigned short)(x & 0xFFFFu)));
    float2 b = __half22float2(dec2h((unsigned short)(x >> 16)));
    f[0] = a.x; f[1] = a.y; f[2] = b.x; f[3] = b.y;
}

// ---------------- grid-wide barrier -------------------------------------------
__device__ __forceinline__ void grid_barrier() {
    __syncthreads();
    if (threadIdx.x == 0) {
        __threadfence();
        unsigned gen = g_gen;
        if (atomicAdd(&g_cnt, 1u) == GRID_SINK - 1) {
            atomicExch(&g_cnt, 0u);
            __threadfence();
            g_gen = gen + 1;
        } else {
            while (g_gen == gen) { }
        }
        __threadfence();   // acquire: CCTL.IVALL flushes L1
    }
    __syncthreads();
}

// ---------------- row squared norms --------------------------------------------
__global__ void rowsq_kernel(const float* __restrict__ z0, const float* __restrict__ z1,
                             const float* __restrict__ z2) {
    int gw = (blockIdx.x * blockDim.x + threadIdx.x) >> 5;
    int lane = threadIdx.x & 31;
    int which = gw >> 12, row = gw & 4095;
    const float* src = which == 0 ? z0 : (which == 1 ? z1 : z2);
    float4 v = *(const float4*)(src + (size_t)row * DD + lane * 4);
    float s = v.x * v.x + v.y * v.y + v.z * v.z + v.w * v.w;
#pragma unroll
    for (int o = 16; o; o >>= 1) s += __shfl_xor_sync(0xffffffffu, s, o);
    if (lane == 0) g_sq[which][row] = s;
}

// ---------------- build K (fp8) for all 3 pairs --------------------------------
__global__ void __launch_bounds__(256) build_kernel(const float* __restrict__ z0,
                                                    const float* __restrict__ z1,
                                                    const float* __restrict__ z2) {
    __shared__ float sx[64][33];
    __shared__ float sy[64][33];
    const int pa[3] = {0, 0, 1};
    const int pb[3] = {1, 2, 2};
    const float* zz[3] = {z0, z1, z2};
    const int p = blockIdx.z;
    const float* x = zz[pa[p]];
    const float* y = zz[pb[p]];

    const int tid = threadIdx.x;
    const int tx = tid & 15, ty = tid >> 4;
    const int row0 = blockIdx.y << 6, col0 = blockIdx.x << 6;

    float acc[4][4] = {};

    for (int kc = 0; kc < DD; kc += 32) {
        __syncthreads();
#pragma unroll
        for (int q = 0; q < 2; q++) {
            int idx = tid + (q << 8);
            int r = idx >> 3, kk = (idx & 7) << 2;
            float4 a = *(const float4*)(x + (size_t)(row0 + r) * DD + kc + kk);
            sx[r][kk] = a.x; sx[r][kk + 1] = a.y; sx[r][kk + 2] = a.z; sx[r][kk + 3] = a.w;
            float4 b = *(const float4*)(y + (size_t)(col0 + r) * DD + kc + kk);
            sy[r][kk] = b.x; sy[r][kk + 1] = b.y; sy[r][kk + 2] = b.z; sy[r][kk + 3] = b.w;
        }
        __syncthreads();
#pragma unroll
        for (int k = 0; k < 32; k++) {
            float xa[4], yb[4];
#pragma unroll
            for (int a = 0; a < 4; a++) xa[a] = sx[ty * 4 + a][k];
#pragma unroll
            for (int b = 0; b < 4; b++) yb[b] = sy[tx * 4 + b][k];
#pragma unroll
            for (int a = 0; a < 4; a++)
#pragma unroll
                for (int b = 0; b < 4; b++)
                    acc[a][b] = fmaf(xa[a], yb[b], acc[a][b]);
        }
    }

    float xs[4], ys[4];
#pragma unroll
    for (int a = 0; a < 4; a++) xs[a] = g_sq[pa[p]][row0 + ty * 4 + a];
#pragma unroll
    for (int b = 0; b < 4; b++) ys[b] = g_sq[pb[p]][col0 + tx * 4 + b];

    const size_t base = (size_t)p * NN * NN;
#pragma unroll
    for (int a = 0; a < 4; a++) {
        size_t off = base + (size_t)(row0 + ty * 4 + a) * NN + col0 + tx * 4;
        float kk[4];
#pragma unroll
        for (int b = 0; b < 4; b++) {
            float c = fmaxf(xs[a] + ys[b] - 2.0f * acc[a][b], 0.0f);
            kk[b] = fmaxf(__expf(-20.0f * c), 0.002f);   // clamp above fp8 underflow
        }
        *(unsigned*)(g_K8 + off) = enc4(kk[0], kk[1], kk[2], kk[3]);
    }
}

// ---------------- persistent fused 3-pair Sinkhorn (fp8 K, half2 math) ---------
__global__ void __launch_bounds__(512, 1) sinkhorn_kernel() {
    __shared__ __align__(16) unsigned char smem_raw[16384];
    __half2* svu = (__half2*)smem_raw;                 // phase A: u bcast [1024] (4KB)
    float* red = (float*)(smem_raw + 4096);            // phase A: [16][128] (8KB)
    __half* svh = (__half*)smem_raw;                   // phase B: v'' [4096] (8KB)

    const int c = blockIdx.x;
    const int tid = threadIdx.x;
    const int lane = tid & 31, w = tid >> 5;           // 16 warps
    const int rb = c >> 5, cb = c & 31;                // phase-A tile: 1024 rows x 128 cols
    const int cg = lane & 7, ro = lane >> 3;           // col-group, row-offset

    if (tid < 32) {
#pragma unroll
        for (int p = 0; p < 3; p++) g_u[p][c * 32 + tid] = 1.0f;
    }
    grid_barrier();

    for (int it = 0; it < ITERS; it++) {
        // ================= Phase A: partial t = K^T u =========================
#pragma unroll 1
        for (int p = 0; p < 3; p++) {
            __syncthreads();
            svu[tid]       = __float2half2_rn(g_u[p][rb * 1024 + tid]);
            svu[tid + 512] = __float2half2_rn(g_u[p][rb * 1024 + tid + 512]);
            __syncthreads();

            const uint4* Ka = (const uint4*)(g_K8 + (size_t)p * NN * NN +
                                             (size_t)(rb * 1024 + w * 64 + ro) * NN +
                                             cb * 128 + cg * 16);
            float t[16];
            __half2 acc[8];
#pragma unroll
            for (int j = 0; j < 8; j++) acc[j] = __half2half2(__ushort_as_half(0));
#pragma unroll
            for (int k = 0; k < 16; k++) t[k] = 0.0f;

#pragma unroll
            for (int i = 0; i < 16; i++) {
                uint4 kr = __ldcg(Ka + (size_t)i * 1024);   // +4 rows
                __half2 uu = svu[w * 64 + i * 4 + ro];
                __half2 kh[8];
                dec16(kr, kh);
#pragma unroll
                for (int j = 0; j < 8; j++) acc[j] = __hfma2(kh[j], uu, acc[j]);
                if (i == 7 || i == 15) {
#pragma unroll
                    for (int j = 0; j < 8; j++) {
                        float2 f = __half22float2(acc[j]);
                        t[j * 2] += f.x;
                        t[j * 2 + 1] += f.y;
                        acc[j] = __half2half2(__ushort_as_half(0));
                    }
                }
            }
            // reduce over ro (lane bits 3,4)
#pragma unroll
            for (int k = 0; k < 16; k++) {
                t[k] += __shfl_xor_sync(0xffffffffu, t[k], 8);
                t[k] += __shfl_xor_sync(0xffffffffu, t[k], 16);
            }
            if (ro == 0) {
#pragma unroll
                for (int k = 0; k < 16; k++) red[w * 128 + cg * 16 + k] = t[k];
            }
            __syncthreads();
            if (tid < 128) {
                float s = red[tid];
#pragma unroll
                for (int w2 = 1; w2 < 16; w2++) s += red[w2 * 128 + tid];
                g_tp[p][rb][cb * 128 + tid] = s;
            }
        }
        grid_barrier();

        // ================= Phase B: u = mu / (K v + eps) ======================
#pragma unroll 1
        for (int p = 0; p < 3; p++) {
            __syncthreads();
            {   // stage v'' = VSCALE/(t+eps) as half[4096]
                const float4* tp0 = (const float4*)g_tp[p][0];
                const float4* tp1 = (const float4*)g_tp[p][1];
                const float4* tp2 = (const float4*)g_tp[p][2];
                const float4* tp3 = (const float4*)g_tp[p][3];
                int a = tid * 2, b = tid * 2 + 1;
                float4 A0 = tp0[a], A1 = tp1[a], A2 = tp2[a], A3 = tp3[a];
                float4 B0 = tp0[b], B1 = tp1[b], B2 = tp2[b], B3 = tp3[b];
                float4 A = make_float4(A0.x + A1.x + A2.x + A3.x, A0.y + A1.y + A2.y + A3.y,
                                       A0.z + A1.z + A2.z + A3.z, A0.w + A1.w + A2.w + A3.w);
                float4 B = make_float4(B0.x + B1.x + B2.x + B3.x, B0.y + B1.y + B2.y + B3.y,
                                       B0.z + B1.z + B2.z + B3.z, B0.w + B1.w + B2.w + B3.w);
                __half2 h0 = __floats2half2_rn(__fdividef(VSCALE, A.x + EPSV),
                                               __fdividef(VSCALE, A.y + EPSV));
                __half2 h1 = __floats2half2_rn(__fdividef(VSCALE, A.z + EPSV),
                                               __fdividef(VSCALE, A.w + EPSV));
                __half2 h2 = __floats2half2_rn(__fdividef(VSCALE, B.x + EPSV),
                                               __fdividef(VSCALE, B.y + EPSV));
                __half2 h3 = __floats2half2_rn(__fdividef(VSCALE, B.z + EPSV),
                                               __fdividef(VSCALE, B.w + EPSV));
                uint4 pk;
                pk.x = *reinterpret_cast<unsigned*>(&h0);
                pk.y = *reinterpret_cast<unsigned*>(&h1);
                pk.z = *reinterpret_cast<unsigned*>(&h2);
                pk.w = *reinterpret_cast<unsigned*>(&h3);
                ((uint4*)svh)[tid] = pk;
            }
            __syncthreads();

            const uint4* sv4 = (const uint4*)svh;
#pragma unroll
            for (int r = 0; r < 2; r++) {
                int row = c * 32 + w * 2 + r;
                const uint4* Kr = (const uint4*)(g_K8 + (size_t)p * NN * NN +
                                                 (size_t)row * NN) + lane;
                __half2 a0 = __half2half2(__ushort_as_half(0));
                __half2 a1 = a0, a2 = a0, a3 = a0;
#pragma unroll
                for (int i = 0; i < 8; i++) {
                    uint4 kr = __ldcg(Kr + i * 32);
                    uint4 v0 = sv4[i * 64 + lane * 2];
                    uint4 v1 = sv4[i * 64 + lane * 2 + 1];
                    __half2 kh[8];
                    dec16(kr, kh);
                    const __half2* vh0 = (const __half2*)&v0;
                    const __half2* vh1 = (const __half2*)&v1;
                    a0 = __hfma2(kh[0], vh0[0], a0);
                    a1 = __hfma2(kh[1], vh0[1], a1);
                    a2 = __hfma2(kh[2], vh0[2], a2);
                    a3 = __hfma2(kh[3], vh0[3], a3);
                    a0 = __hfma2(kh[4], vh1[0], a0);
                    a1 = __hfma2(kh[5], vh1[1], a1);
                    a2 = __hfma2(kh[6], vh1[2], a2);
                    a3 = __hfma2(kh[7], vh1[3], a3);
                }
                float2 f0 = __half22float2(a0), f1 = __half22float2(a1);
                float2 f2 = __half22float2(a2), f3 = __half22float2(a3);
                float acc = (f0.x + f0.y) + (f1.x + f1.y) + (f2.x + f2.y) + (f3.x + f3.y);
#pragma unroll
                for (int o = 16; o; o >>= 1) acc += __shfl_xor_sync(0xffffffffu, acc, o);
                if (lane == 0)
                    g_u[p][row] = __fdividef(MUV, acc * (MUV / VSCALE) + EPSV);
            }
        }
        grid_barrier();
    }
}

// ---------------- loss = sum_ij u_i K_ij C_ij v_j,  C = -reg*ln(K) -------------
__global__ void __launch_bounds__(256) loss_kernel() {
    __shared__ float svec[NN];
    __shared__ double sred[8];
    const int c = blockIdx.x;
    const int p = blockIdx.y;
    const int tid = threadIdx.x;
    const int lane = tid & 31, w = tid >> 5;

#pragma unroll
    for (int k2 = 0; k2 < 16; k2++) {
        int j = tid + k2 * 256;
        float t = g_tp[p][0][j] + g_tp[p][1][j] + g_tp[p][2][j] + g_tp[p][3][j];
        svec[j] = MUV / (t + EPSV);
    }
    __syncthreads();

    const float4* sv4 = (const float4*)svec;
    double dacc = 0.0;
#pragma unroll
    for (int rr = 0; rr < 4; rr++) {
        int row = c * 32 + w * 4 + rr;
        const uint2* Kr = (const uint2*)(g_K8 + (size_t)p * NN * NN + (size_t)row * NN) + lane;
        float acc = 0.0f;
#pragma unroll 2
        for (int i = 0; i < 16; i++) {
            uint2 kr = __ldcs(Kr + i * 32);
            float4 v0 = sv4[(lane + i * 32) * 2];
            float4 v1 = sv4[(lane + i * 32) * 2 + 1];
            float f[8];
            dec4f(kr.x, f);
            dec4f(kr.y, f + 4);
            float vv[8] = {v0.x, v0.y, v0.z, v0.w, v1.x, v1.y, v1.z, v1.w};
#pragma unroll
            for (int j = 0; j < 8; j++) {
                float cc = -REGC * __logf(fmaxf(f[j], 1e-30f));
                acc = fmaf(f[j] * cc, vv[j], acc);
            }
        }
#pragma unroll
        for (int o = 16; o; o >>= 1) acc += __shfl_xor_sync(0xffffffffu, acc, o);
        if (lane == 0) dacc += (double)acc * (double)g_u[p][row];
    }
    if (lane == 0) sred[w] = dacc;
    __syncthreads();
    if (tid == 0) {
        double s = 0.0;
#pragma unroll
        for (int i = 0; i < 8; i++) s += sred[i];
        g_part[p * GRID_SINK + c] = s;
    }
}

// ---------------- final reduction ---------------------------------------------
__global__ void final_kernel(float* out) {
    __shared__ double sd[128];
    int t = threadIdx.x;
    double s = g_part[t] + g_part[t + 128] + g_part[t + 256];
    sd[t] = s;
    __syncthreads();
    for (int o = 64; o; o >>= 1) {
        if (t < o) sd[t] += sd[t + o];
        __syncthreads();
    }
    if (t == 0) out[0] = (float)(sd[0] / 3.0);
}

// ---------------- launch -------------------------------------------------------
extern "C" void kernel_launch(void* const* d_in, const int* in_sizes, int n_in,
                              void* d_out, int out_size) {
    const float* z0 = (const float*)d_in[0];
    const float* z1 = (const float*)d_in[1];
    const float* z2 = (const float*)d_in[2];

    rowsq_kernel<<<1536, 256>>>(z0, z1, z2);
    build_kernel<<<dim3(64, 64, 3), 256>>>(z0, z1, z2);
    sinkhorn_kernel<<<GRID_SINK, 512>>>();
    loss_kernel<<<dim3(GRID_SINK, 3), 256>>>();
    final_kernel<<<1, 128>>>((float*)d_out);
}